// round 3
// baseline (speedup 1.0000x reference)
#include <cuda_runtime.h>
#include <math.h>

// ---------------- problem constants ----------------
#define BB   4
#define TT   1024
#define HID  1024
#define NA   1024
#define NH   64
#define HS   16
#define CTX  1024
#define NC   16     // time chunks for the scan
#define CL   64     // chunk length (NC*CL == TT)

// ---------------- scratch (static device memory: no allocations) ----------------
__device__ float g_k[BB*TT*NA];      // exp(clip(k))
__device__ float g_v[BB*TT*NA];
__device__ float g_r[BB*TT*NA];      // sigmoid(r)
__device__ float g_rwkv[BB*TT*NA];
__device__ float g_Send[BB*NC*NA];
__device__ float g_Ksum[BB*NC*NA];
__device__ float g_cS[BB*NC*NA];
__device__ float g_cK[BB*NC*NA];

// ---------------- packed f32x2 helpers (sm_100+) ----------------
__device__ __forceinline__ void fma2(unsigned long long& d,
                                     unsigned long long a,
                                     unsigned long long b) {
    asm("fma.rn.f32x2 %0, %1, %2, %0;" : "+l"(d) : "l"(a), "l"(b));
}
__device__ __forceinline__ unsigned long long pack2(float lo, float hi) {
    unsigned long long r;
    asm("mov.b64 %0, {%1, %2};" : "=l"(r) : "f"(lo), "f"(hi));
    return r;
}
__device__ __forceinline__ void unpack2(unsigned long long v, float& lo, float& hi) {
    asm("mov.b64 {%0, %1}, %2;" : "=f"(lo), "=f"(hi) : "l"(v));
}

// ---------------- fused SGEMM ----------------
// C[M=4096, N=1024] = A[4096,1024] @ W[1024,1024] + bias, with epilogue act:
//   act 0: none   act 1: exp(clip(v,-60,30))   act 2: sigmoid   act 3: *gamma[t]
// SHIFT=1: A is read from x with RWKV time-shift on channels [0,512).
static const int Bb_M = 128, Bb_N = 128, Bb_K = 16;
static const int LDA_S = Bb_M + 4;   // pad 4 keeps float4 alignment
static const int LDB_S = Bb_N + 4;

template<int SHIFT>
__global__ __launch_bounds__(256, 2)
void gemm_kernel(const float* __restrict__ A, const float* __restrict__ W,
                 const float* __restrict__ bias, const float* __restrict__ gamma,
                 float* __restrict__ out, int act)
{
    __shared__ float As[Bb_K * LDA_S];
    __shared__ float Bs[Bb_K * LDB_S];

    const int tid = threadIdx.x;
    const int tx  = tid & 15;          // N direction (16)
    const int ty  = tid >> 4;          // M direction (16)
    const int rowBase = blockIdx.y * Bb_M;
    const int colBase = blockIdx.x * Bb_N;

    // accumulators: 8 rows x 4 packed column-pairs (= 8x8 fp32)
    unsigned long long acc[8][4];
#pragma unroll
    for (int i = 0; i < 8; i++)
#pragma unroll
        for (int j = 0; j < 4; j++) acc[i][j] = 0ULL;

    // load index mapping
    const int arow = tid >> 2;         // 0..63 (+64 second pass)
    const int acol = (tid & 3) * 4;    // k offset within BK
    const int brow = tid >> 5;         // 0..7 (+8 second pass)
    const int bcol = (tid & 31) * 4;   // n offset, coalesced

    for (int k0 = 0; k0 < HID; k0 += Bb_K) {
        // --- A tile: [BM x BK] -> transposed in SMEM As[k][m]
#pragma unroll
        for (int rr = 0; rr < 2; rr++) {
            const int r    = arow + rr * 64;
            const int grow = rowBase + r;
            const int c    = k0 + acol;       // 16-wide slab never crosses c=512
            float4 val;
            if (SHIFT) {
                const int t = grow & (TT - 1);
                if (c < HID / 2) {
                    if (t > 0) val = *(const float4*)(A + (size_t)(grow - 1) * HID + c);
                    else       val = make_float4(0.f, 0.f, 0.f, 0.f);
                } else {
                    val = *(const float4*)(A + (size_t)grow * HID + c);
                }
            } else {
                val = *(const float4*)(A + (size_t)grow * HID + c);
            }
            As[(acol + 0) * LDA_S + r] = val.x;
            As[(acol + 1) * LDA_S + r] = val.y;
            As[(acol + 2) * LDA_S + r] = val.z;
            As[(acol + 3) * LDA_S + r] = val.w;
        }
        // --- B tile: [BK x BN] direct
#pragma unroll
        for (int rr = 0; rr < 2; rr++) {
            const int r = brow + rr * 8;
            *(float4*)(Bs + r * LDB_S + bcol) =
                *(const float4*)(W + (size_t)(k0 + r) * NA + colBase + bcol);
        }
        __syncthreads();

#pragma unroll
        for (int kk = 0; kk < Bb_K; kk++) {
            const float4 a0 = *(const float4*)(As + kk * LDA_S + ty * 4);
            const float4 a1 = *(const float4*)(As + kk * LDA_S + ty * 4 + 64);
            const float4 b0 = *(const float4*)(Bs + kk * LDB_S + tx * 4);
            const float4 b1 = *(const float4*)(Bs + kk * LDB_S + tx * 4 + 64);
            unsigned long long bb[4];
            bb[0] = pack2(b0.x, b0.y); bb[1] = pack2(b0.z, b0.w);
            bb[2] = pack2(b1.x, b1.y); bb[3] = pack2(b1.z, b1.w);
            const float av[8] = {a0.x, a0.y, a0.z, a0.w, a1.x, a1.y, a1.z, a1.w};
#pragma unroll
            for (int i = 0; i < 8; i++) {
                const unsigned long long a2 = pack2(av[i], av[i]);
#pragma unroll
                for (int j = 0; j < 4; j++) fma2(acc[i][j], a2, bb[j]);
            }
        }
        __syncthreads();
    }

    // --- epilogue ---
#pragma unroll
    for (int i = 0; i < 8; i++) {
        const int grow = rowBase + ty * 4 + ((i < 4) ? i : (64 + i - 4));
        const int t    = grow & (TT - 1);
        const float gm = (act == 3) ? gamma[t] : 1.f;
#pragma unroll
        for (int j = 0; j < 4; j++) {
            float lo, hi;
            unpack2(acc[i][j], lo, hi);
            const int col = colBase + ((j < 2) ? (tx * 4 + j * 2)
                                               : (64 + tx * 4 + (j - 2) * 2));
            float v0 = lo + bias[col];
            float v1 = hi + bias[col + 1];
            if (act == 1) {
                v0 = __expf(fminf(fmaxf(v0, -60.f), 30.f));
                v1 = __expf(fminf(fmaxf(v1, -60.f), 30.f));
                // use accurate expf to be safe on tolerance:
                v0 = expf(fminf(fmaxf(lo + bias[col],     -60.f), 30.f));
                v1 = expf(fminf(fmaxf(hi + bias[col + 1], -60.f), 30.f));
            } else if (act == 2) {
                v0 = 1.f / (1.f + expf(-v0));
                v1 = 1.f / (1.f + expf(-v1));
            } else if (act == 3) {
                v0 *= gm;
                v1 *= gm;
            }
            float2 st = make_float2(v0, v1);
            *(float2*)(out + (size_t)grow * NA + col) = st;
        }
    }
}

// ---------------- chunked linear scan over time ----------------
// S_t = ratio_h * S_{t-1} + w0_h * alpha_t * k_t * v_t ;  ksum_t = ksum_{t-1} + k_t
// Pass A: per-(b,chunk,channel) local scan end-states.
__global__ void pass_scan_local(const float* __restrict__ time_w,
                                const float* __restrict__ time_alpha)
{
    const int n = blockIdx.x * 128 + threadIdx.x;
    const int j = blockIdx.y;
    const int b = blockIdx.z;
    const int h = n >> 4;
    const float wlast = time_w[h * CTX + CTX - 1];
    const float ratio = time_w[h * CTX + CTX - 2] / wlast;
    float S = 0.f, ks = 0.f;
    const size_t base = ((size_t)(b * TT + j * CL)) * NA + n;
    const float* al = time_alpha + h * CTX + j * CL;
#pragma unroll 4
    for (int u = 0; u < CL; u++) {
        const float kk = g_k[base + (size_t)u * NA];
        const float vv = g_v[base + (size_t)u * NA];
        S  = fmaf(S, ratio, wlast * al[u] * kk * vv);
        ks += kk;
    }
    const int o = (b * NC + j) * NA + n;
    g_Send[o] = S;
    g_Ksum[o] = ks;
}

// Pass B: exclusive scan across the NC chunks per channel.
__global__ void pass_scan_carry(const float* __restrict__ time_w)
{
    const int idx = blockIdx.x * 256 + threadIdx.x;   // B*NA threads
    const int n = idx & (NA - 1);
    const int b = idx >> 10;
    const int h = n >> 4;
    const float ratio = time_w[h * CTX + CTX - 2] / time_w[h * CTX + CTX - 1];
    float rL = ratio;
#pragma unroll
    for (int i = 0; i < 6; i++) rL *= rL;   // ratio^64
    float cS = 0.f, cK = 0.f;
    for (int j = 0; j < NC; j++) {
        const int o = (b * NC + j) * NA + n;
        g_cS[o] = cS;
        g_cK[o] = cK;
        cS = cS * rL + g_Send[o];
        cK += g_Ksum[o];
    }
}

// Pass C: replay chunk with carry-in, emit rwkv = sigmoid(r)*beta_t*S_t/ksum_t
__global__ void pass_scan_final(const float* __restrict__ time_w,
                                const float* __restrict__ time_alpha,
                                const float* __restrict__ time_beta)
{
    const int n = blockIdx.x * 128 + threadIdx.x;
    const int j = blockIdx.y;
    const int b = blockIdx.z;
    const int h = n >> 4;
    const float wlast = time_w[h * CTX + CTX - 1];
    const float ratio = time_w[h * CTX + CTX - 2] / wlast;
    const int o = (b * NC + j) * NA + n;
    float S  = g_cS[o];
    float ks = g_cK[o];
    const size_t base = ((size_t)(b * TT + j * CL)) * NA + n;
    const float* al = time_alpha + h * CTX + j * CL;
    const float* be = time_beta  + h * CTX + j * CL;
#pragma unroll 4
    for (int u = 0; u < CL; u++) {
        const size_t off = base + (size_t)u * NA;
        const float kk = g_k[off];
        const float vv = g_v[off];
        const float sr = g_r[off];          // already sigmoid
        S  = fmaf(S, ratio, wlast * al[u] * kk * vv);
        ks += kk;
        g_rwkv[off] = sr * be[u] * S / ks;
    }
}

// ---------------- launch ----------------
extern "C" void kernel_launch(void* const* d_in, const int* in_sizes, int n_in,
                              void* d_out, int out_size)
{
    const float* x          = (const float*)d_in[0];
    const float* time_w     = (const float*)d_in[1];
    const float* time_alpha = (const float*)d_in[2];
    const float* time_beta  = (const float*)d_in[3];
    const float* time_gamma = (const float*)d_in[4];
    const float* Wk = (const float*)d_in[5];
    const float* bk = (const float*)d_in[6];
    const float* Wv = (const float*)d_in[7];
    const float* bv = (const float*)d_in[8];
    const float* Wr = (const float*)d_in[9];
    const float* br = (const float*)d_in[10];
    const float* Wo = (const float*)d_in[11];
    const float* bo = (const float*)d_in[12];
    float* out = (float*)d_out;

    float *gk, *gv, *gr, *grwkv;
    cudaGetSymbolAddress((void**)&gk, g_k);
    cudaGetSymbolAddress((void**)&gv, g_v);
    cudaGetSymbolAddress((void**)&gr, g_r);
    cudaGetSymbolAddress((void**)&grwkv, g_rwkv);

    const dim3 gdim(NA / Bb_N, (BB * TT) / Bb_M, 1);   // (8, 32)

    // K, V, R projections (time-shift fused into A loads, activations in epilogue)
    gemm_kernel<1><<<gdim, 256>>>(x, Wk, bk, nullptr, gk, 1);  // exp(clip)
    gemm_kernel<1><<<gdim, 256>>>(x, Wv, bv, nullptr, gv, 0);
    gemm_kernel<1><<<gdim, 256>>>(x, Wr, br, nullptr, gr, 2);  // sigmoid

    // chunked linear recurrence (wkv + cumsum(k)) -> rwkv
    pass_scan_local <<<dim3(NA / 128, NC, BB), 128>>>(time_w, time_alpha);
    pass_scan_carry <<<(BB * NA) / 256, 256>>>(time_w);
    pass_scan_final <<<dim3(NA / 128, NC, BB), 128>>>(time_w, time_alpha, time_beta);

    // output projection with gamma scaling
    gemm_kernel<0><<<gdim, 256>>>(grwkv, Wo, bo, time_gamma, out, 3);
}

// round 5
// speedup vs baseline: 2.5348x; 2.5348x over previous
#include <cuda_runtime.h>
#include <cuda_bf16.h>
#include <math.h>
#include <stdint.h>

// ---------------- problem constants ----------------
#define BB   4
#define TT   1024
#define HID  1024
#define NA   1024
#define NH   64
#define CTX  1024
#define NC   16
#define CL   64

// ---------------- GEMM tiling ----------------
#define KT          16        // K chunks of 64
#define TILE_BYTES  16384     // 128 rows x 128 bytes (64 bf16)
#define TILE_ELEMS  8192
#define NSTAGE      3
#define STAGE_BYTES 65536     // 4 tiles (A_hi, A_lo, B_hi, B_lo)
#define SMEM_TOTAL  (2048 + NSTAGE * STAGE_BYTES)

// ---------------- static scratch ----------------
__device__ float g_k[BB*TT*NA];
__device__ float g_v[BB*TT*NA];
__device__ float g_r[BB*TT*NA];
__device__ float g_Send[BB*NC*NA];
__device__ float g_Ksum[BB*NC*NA];
__device__ float g_cS[BB*NC*NA];
__device__ float g_cK[BB*NC*NA];
// bf16 hi/lo operand tiles, pre-swizzled (SW128-style XOR on 16B units)
__device__ __align__(16) __nv_bfloat16 g_Ahi[BB*TT*NA];
__device__ __align__(16) __nv_bfloat16 g_Alo[BB*TT*NA];
__device__ __align__(16) __nv_bfloat16 g_Whi[4*HID*NA];
__device__ __align__(16) __nv_bfloat16 g_Wlo[4*HID*NA];

// ---------------- ptx helpers (all baseline, non-'a' features) ----------------
__device__ __forceinline__ uint32_t smem_u32(const void* p) {
    uint32_t a;
    asm("{ .reg .u64 t; cvta.to.shared.u64 t, %1; cvt.u32.u64 %0, t; }" : "=r"(a) : "l"(p));
    return a;
}
#define MBAR_INIT(a, c) \
    asm volatile("mbarrier.init.shared.b64 [%0], %1;" :: "r"(a), "r"(c) : "memory")
#define MBAR_EXPECT_TX(a, b) \
    asm volatile("mbarrier.arrive.expect_tx.shared.b64 _, [%0], %1;" :: "r"(a), "r"(b) : "memory")
#define MBAR_ARRIVE(a) \
    asm volatile("mbarrier.arrive.shared.b64 _, [%0];" :: "r"(a) : "memory")
#define MBAR_WAIT(a, ph) do { \
    asm volatile("{\n\t.reg .pred P;\n\tWL%=:\n\t" \
        "mbarrier.try_wait.parity.acquire.cta.shared::cta.b64 P, [%0], %1, 0x989680;\n\t" \
        "@P bra.uni WD%=;\n\tbra.uni WL%=;\n\tWD%=:\n\t}" \
        :: "r"(a), "r"(ph) : "memory"); } while (0)

__device__ __forceinline__ void bulk_ldg(uint32_t dst, const void* src, uint32_t bytes, uint32_t mbar) {
    asm volatile("cp.async.bulk.shared::cluster.global.mbarrier::complete_tx::bytes [%0], [%1], %2, [%3];"
        :: "r"(dst), "l"((unsigned long long)__cvta_generic_to_global(src)), "r"(bytes), "r"(mbar) : "memory");
}
#define LDSM4(r0, r1, r2, r3, a) \
    asm volatile("ldmatrix.sync.aligned.m8n8.x4.shared.b16 {%0,%1,%2,%3}, [%4];" \
        : "=r"(r0), "=r"(r1), "=r"(r2), "=r"(r3) : "r"(a))

__device__ __forceinline__ void mma16816(float* d, const uint32_t* a, const uint32_t* b) {
    asm volatile("mma.sync.aligned.m16n8k16.row.col.f32.bf16.bf16.f32 "
        "{%0,%1,%2,%3}, {%4,%5,%6,%7}, {%8,%9}, {%0,%1,%2,%3};"
        : "+f"(d[0]), "+f"(d[1]), "+f"(d[2]), "+f"(d[3])
        : "r"(a[0]), "r"(a[1]), "r"(a[2]), "r"(a[3]), "r"(b[0]), "r"(b[1]));
}
__device__ __forceinline__ uint32_t swz(uint32_t b) { return b ^ ((b >> 3) & 0x70); }

// ---------------- conversion: xs (time-shifted) -> swizzled bf16 hi/lo tiles ----------------
__global__ __launch_bounds__(256)
void conv_x_kernel(const float* __restrict__ x)
{
    const int idx = blockIdx.x * 256 + threadIdx.x;
    const int m = idx >> 8;
    const int k = (idx & 255) * 4;
    const int t = m & (TT - 1);
    float4 v;
    if (k < HID / 2) {
        if (t > 0) v = *(const float4*)(x + (size_t)(m - 1) * HID + k);
        else       v = make_float4(0.f, 0.f, 0.f, 0.f);
    } else {
        v = *(const float4*)(x + (size_t)m * HID + k);
    }
    union { __nv_bfloat16 b[4]; uint2 q; } H, L;
    const float vv[4] = {v.x, v.y, v.z, v.w};
#pragma unroll
    for (int i = 0; i < 4; i++) {
        H.b[i] = __float2bfloat16(vv[i]);
        L.b[i] = __float2bfloat16(vv[i] - __bfloat162float(H.b[i]));
    }
    const int tm = m >> 7, r = m & 127, tk = k >> 6, c = k & 63;
    const size_t off = ((size_t)(tm * KT + tk)) * TILE_BYTES + swz(r * 128 + c * 2);
    *(uint2*)((char*)g_Ahi + off) = H.q;
    *(uint2*)((char*)g_Alo + off) = L.q;
}

// ---------------- conversion: W[K,N] -> [n][k] swizzled bf16 hi/lo tiles ----------------
__global__ __launch_bounds__(256)
void conv_w_kernel(const float* __restrict__ W, int widx)
{
    const int idx = blockIdx.x * 256 + threadIdx.x;
    const int n = idx & (NA - 1);
    const int k0 = (idx >> 10) * 8;
    union { __nv_bfloat16 b[8]; uint4 q; } H, L;
#pragma unroll
    for (int i = 0; i < 8; i++) {
        const float v = W[(size_t)(k0 + i) * NA + n];
        H.b[i] = __float2bfloat16(v);
        L.b[i] = __float2bfloat16(v - __bfloat162float(H.b[i]));
    }
    const int tn = n >> 7, r = n & 127, tk = k0 >> 6, c = k0 & 63;
    const size_t off = ((size_t)widx) * (size_t)HID * NA * 2
                     + ((size_t)(tn * KT + tk)) * TILE_BYTES + swz(r * 128 + c * 2);
    *(uint4*)((char*)g_Whi + off) = H.q;
    *(uint4*)((char*)g_Wlo + off) = L.q;
}

// ---------------- HMMA GEMM: C[4096,1024] = A @ W (+bias, +act) ----------------
// act 0: none  1: exp(clip)  2: sigmoid  3: *gamma[t]
// CTA 128x128, 8 warps (4M x 2N), warp tile 32x64, bf16 3-term split precision.
__global__ __launch_bounds__(256, 1)
void gemm_mma(int widx, const float* __restrict__ bias, const float* __restrict__ gamma,
              float* __restrict__ out, int act)
{
    extern __shared__ char smem_raw[];
    uint32_t sb = smem_u32(smem_raw);
    sb = (sb + 1023) & ~1023u;                 // 1KB-align for clean bank pattern
    const int tid = threadIdx.x, l = tid & 31, w = tid >> 5;
    const int wm = w & 3, wn = w >> 2;
    const int tm = blockIdx.y, tn = blockIdx.x;

    if (tid == 0) {
#pragma unroll
        for (int s = 0; s < NSTAGE; s++) {
            MBAR_INIT(sb + 8 * s, 1);          // full (tx-based)
            MBAR_INIT(sb + 64 + 8 * s, 256);   // empty (all threads arrive)
        }
    }
    __syncthreads();

    const __nv_bfloat16* Ahi = g_Ahi + (size_t)tm * KT * TILE_ELEMS;
    const __nv_bfloat16* Alo = g_Alo + (size_t)tm * KT * TILE_ELEMS;
    const __nv_bfloat16* Bh  = g_Whi + (size_t)widx * HID * NA + (size_t)tn * KT * TILE_ELEMS;
    const __nv_bfloat16* Bl  = g_Wlo + (size_t)widx * HID * NA + (size_t)tn * KT * TILE_ELEMS;

    // prologue: fill all stages
    if (tid == 0) {
#pragma unroll
        for (int c = 0; c < NSTAGE; c++) {
            const uint32_t st = sb + 1024 + c * STAGE_BYTES;
            MBAR_EXPECT_TX(sb + 8 * c, STAGE_BYTES);
            bulk_ldg(st,         Ahi + (size_t)c * TILE_ELEMS, TILE_BYTES, sb + 8 * c);
            bulk_ldg(st + 16384, Alo + (size_t)c * TILE_ELEMS, TILE_BYTES, sb + 8 * c);
            bulk_ldg(st + 32768, Bh  + (size_t)c * TILE_ELEMS, TILE_BYTES, sb + 8 * c);
            bulk_ldg(st + 49152, Bl  + (size_t)c * TILE_ELEMS, TILE_BYTES, sb + 8 * c);
        }
    }

    float acc[2][8][4];
#pragma unroll
    for (int i = 0; i < 2; i++)
#pragma unroll
        for (int j = 0; j < 8; j++)
#pragma unroll
            for (int q = 0; q < 4; q++) acc[i][j][q] = 0.f;

    // per-lane ldmatrix row offsets (bytes within a tile), before k-chunk selection
    // A: lanes 0-15 -> rows m..m+15 (k-lo 16B), lanes 16-31 -> same rows (k-hi 16B)
    const uint32_t a_row0 = (uint32_t)(wm * 32 + (l & 15)) * 128;
    const uint32_t a_row1 = a_row0 + 16 * 128;
    const int a_hi16 = (l >> 4);               // 0 or 1: which 16B chunk of the k16 step
    // B: j = l>>3 selects matrix: ntile = 2*ng + (j>>1), chunk = (j&1)
    const int bj = l >> 3;
    const uint32_t b_rowbase = (uint32_t)(wn * 64 + ((bj >> 1) * 8) + (l & 7)) * 128;
    const int b_hi16 = bj & 1;

    for (int c = 0; c < KT; c++) {
        const int s = c % NSTAGE;
        const uint32_t par = (uint32_t)((c / NSTAGE) & 1);
        MBAR_WAIT(sb + 8 * s, par);
        const uint32_t st = sb + 1024 + s * STAGE_BYTES;
        const uint32_t ah = st, al = st + 16384, bh = st + 32768, bl = st + 49152;

#pragma unroll
        for (int ks = 0; ks < 4; ks++) {
            const uint32_t akoff = (uint32_t)(2 * ks + a_hi16) * 16;
            const uint32_t bkoff = (uint32_t)(2 * ks + b_hi16) * 16;
            uint32_t Ah[2][4], Al_[2][4], Bhf[8][2], Blf[8][2];
            LDSM4(Ah[0][0], Ah[0][1], Ah[0][2], Ah[0][3], ah + swz(a_row0 + akoff));
            LDSM4(Ah[1][0], Ah[1][1], Ah[1][2], Ah[1][3], ah + swz(a_row1 + akoff));
            LDSM4(Al_[0][0], Al_[0][1], Al_[0][2], Al_[0][3], al + swz(a_row0 + akoff));
            LDSM4(Al_[1][0], Al_[1][1], Al_[1][2], Al_[1][3], al + swz(a_row1 + akoff));
#pragma unroll
            for (int ng = 0; ng < 4; ng++) {
                const uint32_t boff = swz(b_rowbase + (uint32_t)(ng * 16) * 128 + bkoff);
                LDSM4(Bhf[2*ng][0], Bhf[2*ng][1], Bhf[2*ng+1][0], Bhf[2*ng+1][1], bh + boff);
                LDSM4(Blf[2*ng][0], Blf[2*ng][1], Blf[2*ng+1][0], Blf[2*ng+1][1], bl + boff);
            }
#pragma unroll
            for (int mt = 0; mt < 2; mt++)
#pragma unroll
                for (int nt = 0; nt < 8; nt++) mma16816(acc[mt][nt], Ah[mt], Bhf[nt]);
#pragma unroll
            for (int mt = 0; mt < 2; mt++)
#pragma unroll
                for (int nt = 0; nt < 8; nt++) mma16816(acc[mt][nt], Ah[mt], Blf[nt]);
#pragma unroll
            for (int mt = 0; mt < 2; mt++)
#pragma unroll
                for (int nt = 0; nt < 8; nt++) mma16816(acc[mt][nt], Al_[mt], Bhf[nt]);
        }
        MBAR_ARRIVE(sb + 64 + 8 * s);
        if (tid == 0 && c + NSTAGE < KT) {
            MBAR_WAIT(sb + 64 + 8 * s, par);
            const int cc = c + NSTAGE;
            MBAR_EXPECT_TX(sb + 8 * s, STAGE_BYTES);
            bulk_ldg(st,         Ahi + (size_t)cc * TILE_ELEMS, TILE_BYTES, sb + 8 * s);
            bulk_ldg(st + 16384, Alo + (size_t)cc * TILE_ELEMS, TILE_BYTES, sb + 8 * s);
            bulk_ldg(st + 32768, Bh  + (size_t)cc * TILE_ELEMS, TILE_BYTES, sb + 8 * s);
            bulk_ldg(st + 49152, Bl  + (size_t)cc * TILE_ELEMS, TILE_BYTES, sb + 8 * s);
        }
    }

    // ---- epilogue ----
    const int mrow_base = tm * 128 + wm * 32;
    const int col_base  = tn * 128 + wn * 64;
#pragma unroll
    for (int mt = 0; mt < 2; mt++) {
#pragma unroll
        for (int nt = 0; nt < 8; nt++) {
            const int r0 = mrow_base + mt * 16 + (l >> 2);
            const int cb = col_base + nt * 8 + (l & 3) * 2;
            const float b0 = bias[cb], b1 = bias[cb + 1];
#pragma unroll
            for (int half = 0; half < 2; half++) {
                const int row = r0 + half * 8;
                float v0 = acc[mt][nt][half * 2]     + b0;
                float v1 = acc[mt][nt][half * 2 + 1] + b1;
                if (act == 1) {
                    v0 = expf(fminf(fmaxf(v0, -60.f), 30.f));
                    v1 = expf(fminf(fmaxf(v1, -60.f), 30.f));
                } else if (act == 2) {
                    v0 = 1.f / (1.f + expf(-v0));
                    v1 = 1.f / (1.f + expf(-v1));
                } else if (act == 3) {
                    const float gm = gamma[row & (TT - 1)];
                    v0 *= gm; v1 *= gm;
                }
                *(float2*)(out + (size_t)row * NA + cb) = make_float2(v0, v1);
            }
        }
    }
}

// ---------------- chunked linear scan ----------------
__global__ void pass_scan_local(const float* __restrict__ time_w,
                                const float* __restrict__ time_alpha)
{
    const int n = blockIdx.x * 128 + threadIdx.x;
    const int j = blockIdx.y;
    const int b = blockIdx.z;
    const int h = n >> 4;
    const float wlast = time_w[h * CTX + CTX - 1];
    const float ratio = time_w[h * CTX + CTX - 2] / wlast;
    float S = 0.f, ks = 0.f;
    const size_t base = ((size_t)(b * TT + j * CL)) * NA + n;
    const float* al = time_alpha + h * CTX + j * CL;
#pragma unroll 4
    for (int u = 0; u < CL; u++) {
        const float kk = g_k[base + (size_t)u * NA];
        const float vv = g_v[base + (size_t)u * NA];
        S  = fmaf(S, ratio, wlast * al[u] * kk * vv);
        ks += kk;
    }
    const int o = (b * NC + j) * NA + n;
    g_Send[o] = S;
    g_Ksum[o] = ks;
}

__global__ void pass_scan_carry(const float* __restrict__ time_w)
{
    const int idx = blockIdx.x * 256 + threadIdx.x;
    const int n = idx & (NA - 1);
    const int b = idx >> 10;
    const int h = n >> 4;
    const float ratio = time_w[h * CTX + CTX - 2] / time_w[h * CTX + CTX - 1];
    float rL = ratio;
#pragma unroll
    for (int i = 0; i < 6; i++) rL *= rL;   // ratio^64
    float cS = 0.f, cK = 0.f;
    for (int j = 0; j < NC; j++) {
        const int o = (b * NC + j) * NA + n;
        g_cS[o] = cS;
        g_cK[o] = cK;
        cS = cS * rL + g_Send[o];
        cK += g_Ksum[o];
    }
}

// final: rwkv = sigmoid(r)*beta*S/ks written directly as swizzled bf16 hi/lo A-tiles
__global__ void pass_scan_final(const float* __restrict__ time_w,
                                const float* __restrict__ time_alpha,
                                const float* __restrict__ time_beta)
{
    const int n = blockIdx.x * 128 + threadIdx.x;
    const int j = blockIdx.y;
    const int b = blockIdx.z;
    const int h = n >> 4;
    const float wlast = time_w[h * CTX + CTX - 1];
    const float ratio = time_w[h * CTX + CTX - 2] / wlast;
    const int o = (b * NC + j) * NA + n;
    float S  = g_cS[o];
    float ks = g_cK[o];
    const size_t base = ((size_t)(b * TT + j * CL)) * NA + n;
    const float* al = time_alpha + h * CTX + j * CL;
    const float* be = time_beta  + h * CTX + j * CL;
    const int tk = n >> 6, c = n & 63;
#pragma unroll 4
    for (int u = 0; u < CL; u++) {
        const size_t off = base + (size_t)u * NA;
        const float kk = g_k[off];
        const float vv = g_v[off];
        const float sr = g_r[off];
        S  = fmaf(S, ratio, wlast * al[u] * kk * vv);
        ks += kk;
        const float val = sr * be[u] * S / ks;
        const __nv_bfloat16 hi = __float2bfloat16(val);
        const __nv_bfloat16 lo = __float2bfloat16(val - __bfloat162float(hi));
        const int tglob = j * CL + u;
        const int tmb = b * 8 + (tglob >> 7);
        const int r = tglob & 127;
        const size_t toff = ((size_t)(tmb * KT + tk)) * TILE_BYTES + swz(r * 128 + c * 2);
        *(__nv_bfloat16*)((char*)g_Ahi + toff) = hi;
        *(__nv_bfloat16*)((char*)g_Alo + toff) = lo;
    }
}

// ---------------- launch ----------------
extern "C" void kernel_launch(void* const* d_in, const int* in_sizes, int n_in,
                              void* d_out, int out_size)
{
    const float* x          = (const float*)d_in[0];
    const float* time_w     = (const float*)d_in[1];
    const float* time_alpha = (const float*)d_in[2];
    const float* time_beta  = (const float*)d_in[3];
    const float* time_gamma = (const float*)d_in[4];
    const float* Wk = (const float*)d_in[5];
    const float* bk = (const float*)d_in[6];
    const float* Wv = (const float*)d_in[7];
    const float* bv = (const float*)d_in[8];
    const float* Wr = (const float*)d_in[9];
    const float* br = (const float*)d_in[10];
    const float* Wo = (const float*)d_in[11];
    const float* bo = (const float*)d_in[12];
    float* out = (float*)d_out;

    float *gk, *gv, *gr;
    cudaGetSymbolAddress((void**)&gk, g_k);
    cudaGetSymbolAddress((void**)&gv, g_v);
    cudaGetSymbolAddress((void**)&gr, g_r);

    cudaFuncSetAttribute(gemm_mma, cudaFuncAttributeMaxDynamicSharedMemorySize, SMEM_TOTAL);

    // operand conversions
    conv_x_kernel<<<4096, 256>>>(x);
    conv_w_kernel<<<512, 256>>>(Wk, 0);
    conv_w_kernel<<<512, 256>>>(Wv, 1);
    conv_w_kernel<<<512, 256>>>(Wr, 2);
    conv_w_kernel<<<512, 256>>>(Wo, 3);

    const dim3 gdim(NA / 128, (BB * TT) / 128, 1);   // (8, 32)
    gemm_mma<<<gdim, 256, SMEM_TOTAL>>>(0, bk, nullptr, gk, 1);  // K -> exp(clip)
    gemm_mma<<<gdim, 256, SMEM_TOTAL>>>(1, bv, nullptr, gv, 0);  // V
    gemm_mma<<<gdim, 256, SMEM_TOTAL>>>(2, br, nullptr, gr, 2);  // R -> sigmoid

    pass_scan_local <<<dim3(NA / 128, NC, BB), 128>>>(time_w, time_alpha);
    pass_scan_carry <<<(BB * NA) / 256, 256>>>(time_w);
    pass_scan_final <<<dim3(NA / 128, NC, BB), 128>>>(time_w, time_alpha, time_beta);

    gemm_mma<<<gdim, 256, SMEM_TOTAL>>>(3, bo, time_gamma, out, 3); // O -> *gamma
}

// round 6
// speedup vs baseline: 2.7877x; 1.0998x over previous
#include <cuda_runtime.h>
#include <cuda_bf16.h>
#include <math.h>
#include <stdint.h>

// ---------------- problem constants ----------------
#define BB   4
#define TT   1024
#define HID  1024
#define NA   1024
#define NH   64
#define CTX  1024
#define NC   16
#define CL   64

// ---------------- GEMM tiling ----------------
#define KT          16        // K chunks of 64
#define TILE_BYTES  16384     // bf16 tile: 128 rows x 128 bytes
#define TILE_ELEMS  8192
#define TF_TILE_F   8192      // tf32 tile: 8192 floats = 32KB (128x64)
#define NSTAGE      3
#define STAGE_BYTES 65536
#define SMEM_TOTAL  (2048 + NSTAGE * STAGE_BYTES)

// ---------------- static scratch ----------------
__device__ float g_k[BB*TT*NA];
__device__ float g_v[BB*TT*NA];
__device__ float g_r[BB*TT*NA];
__device__ float g_Send[BB*NC*NA];
__device__ float g_Ksum[BB*NC*NA];
__device__ float g_cS[BB*NC*NA];
__device__ float g_cK[BB*NC*NA];
// tf32 fragment-packed operands for K/V/R projections
__device__ __align__(16) float g_Atf[BB*TT*HID];       // 512 tiles
__device__ __align__(16) float g_Wtf[3*HID*NA];        // 384 tiles
// bf16 hi/lo swizzled tiles for the Wo GEMM (A written by scan, W by conv)
__device__ __align__(16) __nv_bfloat16 g_Ahi[BB*TT*NA];
__device__ __align__(16) __nv_bfloat16 g_Alo[BB*TT*NA];
__device__ __align__(16) __nv_bfloat16 g_Whi[HID*NA];
__device__ __align__(16) __nv_bfloat16 g_Wlo[HID*NA];

// ---------------- ptx helpers (baseline features only) ----------------
__device__ __forceinline__ uint32_t smem_u32(const void* p) {
    uint32_t a;
    asm("{ .reg .u64 t; cvta.to.shared.u64 t, %1; cvt.u32.u64 %0, t; }" : "=r"(a) : "l"(p));
    return a;
}
#define MBAR_INIT(a, c) \
    asm volatile("mbarrier.init.shared.b64 [%0], %1;" :: "r"(a), "r"(c) : "memory")
#define MBAR_EXPECT_TX(a, b) \
    asm volatile("mbarrier.arrive.expect_tx.shared.b64 _, [%0], %1;" :: "r"(a), "r"(b) : "memory")
#define MBAR_ARRIVE(a) \
    asm volatile("mbarrier.arrive.shared.b64 _, [%0];" :: "r"(a) : "memory")
#define MBAR_WAIT(a, ph) do { \
    asm volatile("{\n\t.reg .pred P;\n\tWL%=:\n\t" \
        "mbarrier.try_wait.parity.acquire.cta.shared::cta.b64 P, [%0], %1, 0x989680;\n\t" \
        "@P bra.uni WD%=;\n\tbra.uni WL%=;\n\tWD%=:\n\t}" \
        :: "r"(a), "r"(ph) : "memory"); } while (0)

__device__ __forceinline__ void bulk_ldg(uint32_t dst, const void* src, uint32_t bytes, uint32_t mbar) {
    asm volatile("cp.async.bulk.shared::cluster.global.mbarrier::complete_tx::bytes [%0], [%1], %2, [%3];"
        :: "r"(dst), "l"((unsigned long long)__cvta_generic_to_global(src)), "r"(bytes), "r"(mbar) : "memory");
}
#define LDSM4(r0, r1, r2, r3, a) \
    asm volatile("ldmatrix.sync.aligned.m8n8.x4.shared.b16 {%0,%1,%2,%3}, [%4];" \
        : "=r"(r0), "=r"(r1), "=r"(r2), "=r"(r3) : "r"(a))

__device__ __forceinline__ void mma16816(float* d, const uint32_t* a, const uint32_t* b) {
    asm volatile("mma.sync.aligned.m16n8k16.row.col.f32.bf16.bf16.f32 "
        "{%0,%1,%2,%3}, {%4,%5,%6,%7}, {%8,%9}, {%0,%1,%2,%3};"
        : "+f"(d[0]), "+f"(d[1]), "+f"(d[2]), "+f"(d[3])
        : "r"(a[0]), "r"(a[1]), "r"(a[2]), "r"(a[3]), "r"(b[0]), "r"(b[1]));
}
__device__ __forceinline__ void mma1688tf(float* d, const uint32_t* a, const uint32_t* b) {
    asm volatile("mma.sync.aligned.m16n8k8.row.col.f32.tf32.tf32.f32 "
        "{%0,%1,%2,%3}, {%4,%5,%6,%7}, {%8,%9}, {%0,%1,%2,%3};"
        : "+f"(d[0]), "+f"(d[1]), "+f"(d[2]), "+f"(d[3])
        : "r"(a[0]), "r"(a[1]), "r"(a[2]), "r"(a[3]), "r"(b[0]), "r"(b[1]));
}
__device__ __forceinline__ uint32_t swz(uint32_t b) { return b ^ ((b >> 3) & 0x70); }
__device__ __forceinline__ uint32_t tf32r(float v) {
    uint32_t r;
    asm("cvt.rna.tf32.f32 %0, %1;" : "=r"(r) : "f"(v));
    return r;
}
// x with RWKV time shift
__device__ __forceinline__ float ldx(const float* __restrict__ x, int m, int k) {
    const int t = m & (TT - 1);
    if (k < HID / 2) return (t > 0) ? x[(size_t)(m - 1) * HID + k] : 0.f;
    return x[(size_t)m * HID + k];
}

// ---------------- conv: xs -> tf32 fragment-packed A tiles ----------------
// A frag map (mma.m16n8k8.tf32): a0=(g,t), a1=(g+8,t), a2=(g,t+4), a3=(g+8,t+4)
__global__ __launch_bounds__(256)
void conv_x_tf(const float* __restrict__ x)
{
    const int idx = blockIdx.x * 256 + threadIdx.x;   // 512 tiles * 64 g * 32 l
    const int l = idx & 31;
    const int g = (idx >> 5) & 63;       // g = s*8 + mf
    const int tile = idx >> 11;          // tile = tm*16 + tk
    const int tm = tile >> 4, tk = tile & 15;
    const int s = g >> 3, mf = g & 7;
    const int m0 = tm * 128 + mf * 16 + (l >> 2);
    const int k0 = tk * 64 + s * 8 + (l & 3);
    float4 f;
    f.x = ldx(x, m0,     k0);
    f.y = ldx(x, m0 + 8, k0);
    f.z = ldx(x, m0,     k0 + 4);
    f.w = ldx(x, m0 + 8, k0 + 4);
    uint4 q;
    q.x = tf32r(f.x); q.y = tf32r(f.y); q.z = tf32r(f.z); q.w = tf32r(f.w);
    *(uint4*)(g_Atf + (size_t)tile * TF_TILE_F + (size_t)(g * 32 + l) * 4) = q;
}

// ---------------- conv: Wk/Wv/Wr -> tf32 fragment-packed B tiles ----------------
// B frag map: b0=(k=t, n=g), b1=(k=t+4, n=g)
__global__ __launch_bounds__(256)
void conv_w_tf(const float* __restrict__ Wk, const float* __restrict__ Wv,
               const float* __restrict__ Wr)
{
    const int idx = blockIdx.x * 256 + threadIdx.x;   // 384 tiles * 128 g * 32 l
    const int l = idx & 31;
    const int g = (idx >> 5) & 127;      // g = s*16 + f
    const int tile = idx >> 12;          // tile = widx*128 + tn*16 + tk
    const int widx = tile >> 7;
    const int rem = tile & 127;
    const int tn = rem >> 4, tk = rem & 15;
    const int s = g >> 4, f = g & 15;
    const int k0 = tk * 64 + s * 8 + (l & 3);
    const int n0 = tn * 128 + f * 8 + (l >> 2);
    const float* W = (widx == 0) ? Wk : (widx == 1) ? Wv : Wr;
    uint2 q;
    q.x = tf32r(W[(size_t)k0 * NA + n0]);
    q.y = tf32r(W[(size_t)(k0 + 4) * NA + n0]);
    *(uint2*)(g_Wtf + (size_t)tile * TF_TILE_F + (size_t)(g * 32 + l) * 2) = q;
}

// ---------------- conv: Wo -> bf16 hi/lo swizzled tiles ----------------
__global__ __launch_bounds__(256)
void conv_w_bf(const float* __restrict__ W)
{
    const int idx = blockIdx.x * 256 + threadIdx.x;
    const int n = idx & (NA - 1);
    const int k0 = (idx >> 10) * 8;
    union { __nv_bfloat16 b[8]; uint4 q; } H, L;
#pragma unroll
    for (int i = 0; i < 8; i++) {
        const float v = W[(size_t)(k0 + i) * NA + n];
        H.b[i] = __float2bfloat16(v);
        L.b[i] = __float2bfloat16(v - __bfloat162float(H.b[i]));
    }
    const int tn = n >> 7, r = n & 127, tk = k0 >> 6, c = k0 & 63;
    const size_t off = ((size_t)(tn * KT + tk)) * TILE_BYTES + swz(r * 128 + c * 2);
    *(uint4*)((char*)g_Whi + off) = H.q;
    *(uint4*)((char*)g_Wlo + off) = L.q;
}

// ---------------- tf32 GEMM: fused K/V/R projections ----------------
// grid (24, 32): widx = bx>>3 selects weight/output/act, tn = bx&7.
__global__ __launch_bounds__(256, 1)
void gemm_tf(const float* __restrict__ bk, const float* __restrict__ bv,
             const float* __restrict__ br)
{
    extern __shared__ char smem_raw[];
    char* smem_al = (char*)(((uintptr_t)smem_raw + 1023) & ~(uintptr_t)1023);
    const uint32_t sb = smem_u32(smem_al);
    const int tid = threadIdx.x, l = tid & 31, w = tid >> 5;
    const int wm = w & 3, wn = w >> 2;
    const int tm = blockIdx.y;
    const int widx = blockIdx.x >> 3, tn = blockIdx.x & 7;

    if (tid == 0) {
#pragma unroll
        for (int s = 0; s < NSTAGE; s++) {
            MBAR_INIT(sb + 8 * s, 1);
            MBAR_INIT(sb + 64 + 8 * s, 256);
        }
    }
    __syncthreads();

    const float* A = g_Atf + (size_t)tm * KT * TF_TILE_F;
    const float* Bw = g_Wtf + ((size_t)widx * 8 + tn) * KT * TF_TILE_F;

    if (tid == 0) {
#pragma unroll
        for (int c = 0; c < NSTAGE; c++) {
            const uint32_t st = sb + 1024 + c * STAGE_BYTES;
            MBAR_EXPECT_TX(sb + 8 * c, STAGE_BYTES);
            bulk_ldg(st,         A  + (size_t)c * TF_TILE_F, 32768, sb + 8 * c);
            bulk_ldg(st + 32768, Bw + (size_t)c * TF_TILE_F, 32768, sb + 8 * c);
        }
    }

    float acc[2][8][4];
#pragma unroll
    for (int i = 0; i < 2; i++)
#pragma unroll
        for (int j = 0; j < 8; j++)
#pragma unroll
            for (int q = 0; q < 4; q++) acc[i][j][q] = 0.f;

    for (int c = 0; c < KT; c++) {
        const int s = c % NSTAGE;
        const uint32_t par = (uint32_t)((c / NSTAGE) & 1);
        MBAR_WAIT(sb + 8 * s, par);
        char* stp = smem_al + 1024 + s * STAGE_BYTES;
        char* bp  = stp + 32768;

#pragma unroll
        for (int ks = 0; ks < 8; ks++) {
            uint32_t Af[2][4];
            uint32_t Bf[8][2];
#pragma unroll
            for (int i = 0; i < 2; i++) {
                uint4 q = *(const uint4*)(stp + ((size_t)((ks * 8 + wm * 2 + i) * 32 + l)) * 16);
                Af[i][0] = q.x; Af[i][1] = q.y; Af[i][2] = q.z; Af[i][3] = q.w;
            }
#pragma unroll
            for (int f = 0; f < 8; f++) {
                uint2 q = *(const uint2*)(bp + ((size_t)((ks * 16 + wn * 8 + f) * 32 + l)) * 8);
                Bf[f][0] = q.x; Bf[f][1] = q.y;
            }
#pragma unroll
            for (int mt = 0; mt < 2; mt++)
#pragma unroll
                for (int nt = 0; nt < 8; nt++) mma1688tf(acc[mt][nt], Af[mt], Bf[nt]);
        }
        MBAR_ARRIVE(sb + 64 + 8 * s);
        if (tid == 0 && c + NSTAGE < KT) {
            MBAR_WAIT(sb + 64 + 8 * s, par);
            const int cc = c + NSTAGE;
            const uint32_t st = sb + 1024 + s * STAGE_BYTES;
            MBAR_EXPECT_TX(sb + 8 * s, STAGE_BYTES);
            bulk_ldg(st,         A  + (size_t)cc * TF_TILE_F, 32768, sb + 8 * s);
            bulk_ldg(st + 32768, Bw + (size_t)cc * TF_TILE_F, 32768, sb + 8 * s);
        }
    }

    // epilogue
    const float* bias = (widx == 0) ? bk : (widx == 1) ? bv : br;
    float* out = (widx == 0) ? g_k : (widx == 1) ? g_v : g_r;
    const int act = (widx == 0) ? 1 : (widx == 1) ? 0 : 2;
    const int mrow_base = tm * 128 + wm * 32;
    const int col_base  = tn * 128 + wn * 64;
#pragma unroll
    for (int mt = 0; mt < 2; mt++) {
#pragma unroll
        for (int nt = 0; nt < 8; nt++) {
            const int r0 = mrow_base + mt * 16 + (l >> 2);
            const int cb = col_base + nt * 8 + (l & 3) * 2;
            const float b0 = bias[cb], b1 = bias[cb + 1];
#pragma unroll
            for (int half = 0; half < 2; half++) {
                const int row = r0 + half * 8;
                float v0 = acc[mt][nt][half * 2]     + b0;
                float v1 = acc[mt][nt][half * 2 + 1] + b1;
                if (act == 1) {
                    v0 = expf(fminf(fmaxf(v0, -60.f), 30.f));
                    v1 = expf(fminf(fmaxf(v1, -60.f), 30.f));
                } else if (act == 2) {
                    v0 = 1.f / (1.f + expf(-v0));
                    v1 = 1.f / (1.f + expf(-v1));
                }
                *(float2*)(out + (size_t)row * NA + cb) = make_float2(v0, v1);
            }
        }
    }
}

// ---------------- bf16 3-term GEMM (Wo path, unchanged from R5) ----------------
__global__ __launch_bounds__(256, 1)
void gemm_mma(const float* __restrict__ bias, const float* __restrict__ gamma,
              float* __restrict__ out)
{
    extern __shared__ char smem_raw[];
    uint32_t sb = smem_u32(smem_raw);
    sb = (sb + 1023) & ~1023u;
    const int tid = threadIdx.x, l = tid & 31, w = tid >> 5;
    const int wm = w & 3, wn = w >> 2;
    const int tm = blockIdx.y, tn = blockIdx.x;

    if (tid == 0) {
#pragma unroll
        for (int s = 0; s < NSTAGE; s++) {
            MBAR_INIT(sb + 8 * s, 1);
            MBAR_INIT(sb + 64 + 8 * s, 256);
        }
    }
    __syncthreads();

    const __nv_bfloat16* Ahi = g_Ahi + (size_t)tm * KT * TILE_ELEMS;
    const __nv_bfloat16* Alo = g_Alo + (size_t)tm * KT * TILE_ELEMS;
    const __nv_bfloat16* Bh  = g_Whi + (size_t)tn * KT * TILE_ELEMS;
    const __nv_bfloat16* Bl  = g_Wlo + (size_t)tn * KT * TILE_ELEMS;

    if (tid == 0) {
#pragma unroll
        for (int c = 0; c < NSTAGE; c++) {
            const uint32_t st = sb + 1024 + c * STAGE_BYTES;
            MBAR_EXPECT_TX(sb + 8 * c, STAGE_BYTES);
            bulk_ldg(st,         Ahi + (size_t)c * TILE_ELEMS, TILE_BYTES, sb + 8 * c);
            bulk_ldg(st + 16384, Alo + (size_t)c * TILE_ELEMS, TILE_BYTES, sb + 8 * c);
            bulk_ldg(st + 32768, Bh  + (size_t)c * TILE_ELEMS, TILE_BYTES, sb + 8 * c);
            bulk_ldg(st + 49152, Bl  + (size_t)c * TILE_ELEMS, TILE_BYTES, sb + 8 * c);
        }
    }

    float acc[2][8][4];
#pragma unroll
    for (int i = 0; i < 2; i++)
#pragma unroll
        for (int j = 0; j < 8; j++)
#pragma unroll
            for (int q = 0; q < 4; q++) acc[i][j][q] = 0.f;

    const uint32_t a_row0 = (uint32_t)(wm * 32 + (l & 15)) * 128;
    const uint32_t a_row1 = a_row0 + 16 * 128;
    const int a_hi16 = (l >> 4);
    const int bj = l >> 3;
    const uint32_t b_rowbase = (uint32_t)(wn * 64 + ((bj >> 1) * 8) + (l & 7)) * 128;
    const int b_hi16 = bj & 1;

    for (int c = 0; c < KT; c++) {
        const int s = c % NSTAGE;
        const uint32_t par = (uint32_t)((c / NSTAGE) & 1);
        MBAR_WAIT(sb + 8 * s, par);
        const uint32_t st = sb + 1024 + s * STAGE_BYTES;
        const uint32_t ah = st, al = st + 16384, bh = st + 32768, bl = st + 49152;

#pragma unroll
        for (int ks = 0; ks < 4; ks++) {
            const uint32_t akoff = (uint32_t)(2 * ks + a_hi16) * 16;
            const uint32_t bkoff = (uint32_t)(2 * ks + b_hi16) * 16;
            uint32_t Ah[2][4], Al_[2][4], Bhf[8][2], Blf[8][2];
            LDSM4(Ah[0][0], Ah[0][1], Ah[0][2], Ah[0][3], ah + swz(a_row0 + akoff));
            LDSM4(Ah[1][0], Ah[1][1], Ah[1][2], Ah[1][3], ah + swz(a_row1 + akoff));
            LDSM4(Al_[0][0], Al_[0][1], Al_[0][2], Al_[0][3], al + swz(a_row0 + akoff));
            LDSM4(Al_[1][0], Al_[1][1], Al_[1][2], Al_[1][3], al + swz(a_row1 + akoff));
#pragma unroll
            for (int ng = 0; ng < 4; ng++) {
                const uint32_t boff = swz(b_rowbase + (uint32_t)(ng * 16) * 128 + bkoff);
                LDSM4(Bhf[2*ng][0], Bhf[2*ng][1], Bhf[2*ng+1][0], Bhf[2*ng+1][1], bh + boff);
                LDSM4(Blf[2*ng][0], Blf[2*ng][1], Blf[2*ng+1][0], Blf[2*ng+1][1], bl + boff);
            }
#pragma unroll
            for (int mt = 0; mt < 2; mt++)
#pragma unroll
                for (int nt = 0; nt < 8; nt++) mma16816(acc[mt][nt], Ah[mt], Bhf[nt]);
#pragma unroll
            for (int mt = 0; mt < 2; mt++)
#pragma unroll
                for (int nt = 0; nt < 8; nt++) mma16816(acc[mt][nt], Ah[mt], Blf[nt]);
#pragma unroll
            for (int mt = 0; mt < 2; mt++)
#pragma unroll
                for (int nt = 0; nt < 8; nt++) mma16816(acc[mt][nt], Al_[mt], Bhf[nt]);
        }
        MBAR_ARRIVE(sb + 64 + 8 * s);
        if (tid == 0 && c + NSTAGE < KT) {
            MBAR_WAIT(sb + 64 + 8 * s, par);
            const int cc = c + NSTAGE;
            MBAR_EXPECT_TX(sb + 8 * s, STAGE_BYTES);
            bulk_ldg(st,         Ahi + (size_t)cc * TILE_ELEMS, TILE_BYTES, sb + 8 * s);
            bulk_ldg(st + 16384, Alo + (size_t)cc * TILE_ELEMS, TILE_BYTES, sb + 8 * s);
            bulk_ldg(st + 32768, Bh  + (size_t)cc * TILE_ELEMS, TILE_BYTES, sb + 8 * s);
            bulk_ldg(st + 49152, Bl  + (size_t)cc * TILE_ELEMS, TILE_BYTES, sb + 8 * s);
        }
    }

    const int mrow_base = tm * 128 + wm * 32;
    const int col_base  = tn * 128 + wn * 64;
#pragma unroll
    for (int mt = 0; mt < 2; mt++) {
#pragma unroll
        for (int nt = 0; nt < 8; nt++) {
            const int r0 = mrow_base + mt * 16 + (l >> 2);
            const int cb = col_base + nt * 8 + (l & 3) * 2;
            const float b0 = bias[cb], b1 = bias[cb + 1];
#pragma unroll
            for (int half = 0; half < 2; half++) {
                const int row = r0 + half * 8;
                const float gm = gamma[row & (TT - 1)];
                const float v0 = (acc[mt][nt][half * 2]     + b0) * gm;
                const float v1 = (acc[mt][nt][half * 2 + 1] + b1) * gm;
                *(float2*)(out + (size_t)row * NA + cb) = make_float2(v0, v1);
            }
        }
    }
}

// ---------------- chunked linear scan (float2 per thread) ----------------
__global__ void pass_scan_local(const float* __restrict__ time_w,
                                const float* __restrict__ time_alpha)
{
    const int p = blockIdx.x * 128 + threadIdx.x;   // channel pair
    const int n = p * 2;
    const int j = blockIdx.y;
    const int b = blockIdx.z;
    const int h = n >> 4;
    const float wlast = time_w[h * CTX + CTX - 1];
    const float ratio = time_w[h * CTX + CTX - 2] / wlast;
    float S0 = 0.f, S1 = 0.f, k0 = 0.f, k1 = 0.f;
    const size_t base = ((size_t)(b * TT + j * CL)) * NA + n;
    const float* al = time_alpha + h * CTX + j * CL;
#pragma unroll 4
    for (int u = 0; u < CL; u++) {
        const float2 kk = *(const float2*)(g_k + base + (size_t)u * NA);
        const float2 vv = *(const float2*)(g_v + base + (size_t)u * NA);
        const float wa = wlast * al[u];
        S0 = fmaf(S0, ratio, wa * kk.x * vv.x);
        S1 = fmaf(S1, ratio, wa * kk.y * vv.y);
        k0 += kk.x; k1 += kk.y;
    }
    const int o = (b * NC + j) * NA + n;
    *(float2*)(g_Send + o) = make_float2(S0, S1);
    *(float2*)(g_Ksum + o) = make_float2(k0, k1);
}

__global__ void pass_scan_carry(const float* __restrict__ time_w)
{
    const int idx = blockIdx.x * 256 + threadIdx.x;
    const int n = idx & (NA - 1);
    const int b = idx >> 10;
    const int h = n >> 4;
    const float ratio = time_w[h * CTX + CTX - 2] / time_w[h * CTX + CTX - 1];
    float rL = ratio;
#pragma unroll
    for (int i = 0; i < 6; i++) rL *= rL;   // ratio^64
    float cS = 0.f, cK = 0.f;
    for (int j = 0; j < NC; j++) {
        const int o = (b * NC + j) * NA + n;
        g_cS[o] = cS;
        g_cK[o] = cK;
        cS = cS * rL + g_Send[o];
        cK += g_Ksum[o];
    }
}

__device__ __forceinline__ uint32_t pack_bf2(float a, float b) {
    __nv_bfloat162 t = __floats2bfloat162_rn(a, b);
    return *(uint32_t*)&t;
}

// final: rwkv = sigmoid(r)*beta*S/ks, written as swizzled bf16 hi/lo A-tiles
__global__ void pass_scan_final(const float* __restrict__ time_w,
                                const float* __restrict__ time_alpha,
                                const float* __restrict__ time_beta)
{
    const int p = blockIdx.x * 128 + threadIdx.x;
    const int n = p * 2;
    const int j = blockIdx.y;
    const int b = blockIdx.z;
    const int h = n >> 4;
    const float wlast = time_w[h * CTX + CTX - 1];
    const float ratio = time_w[h * CTX + CTX - 2] / wlast;
    const int o = (b * NC + j) * NA + n;
    float2 S  = *(float2*)(g_cS + o);
    float2 ks = *(float2*)(g_cK + o);
    const size_t base = ((size_t)(b * TT + j * CL)) * NA + n;
    const float* al = time_alpha + h * CTX + j * CL;
    const float* be = time_beta  + h * CTX + j * CL;
    const int tk = n >> 6, c = n & 63;
#pragma unroll 4
    for (int u = 0; u < CL; u++) {
        const size_t off = base + (size_t)u * NA;
        const float2 kk = *(const float2*)(g_k + off);
        const float2 vv = *(const float2*)(g_v + off);
        const float2 sr = *(const float2*)(g_r + off);
        const float wa = wlast * al[u];
        S.x = fmaf(S.x, ratio, wa * kk.x * vv.x);
        S.y = fmaf(S.y, ratio, wa * kk.y * vv.y);
        ks.x += kk.x; ks.y += kk.y;
        const float v0 = sr.x * be[u] * S.x / ks.x;
        const float v1 = sr.y * be[u] * S.y / ks.y;
        const float h0 = __bfloat162float(__float2bfloat16(v0));
        const float h1 = __bfloat162float(__float2bfloat16(v1));
        const int tglob = j * CL + u;
        const int tmb = b * 8 + (tglob >> 7);
        const int r = tglob & 127;
        const size_t toff = ((size_t)(tmb * KT + tk)) * TILE_BYTES + swz(r * 128 + c * 2);
        *(uint32_t*)((char*)g_Ahi + toff) = pack_bf2(v0, v1);
        *(uint32_t*)((char*)g_Alo + toff) = pack_bf2(v0 - h0, v1 - h1);
    }
}

// ---------------- launch ----------------
extern "C" void kernel_launch(void* const* d_in, const int* in_sizes, int n_in,
                              void* d_out, int out_size)
{
    const float* x          = (const float*)d_in[0];
    const float* time_w     = (const float*)d_in[1];
    const float* time_alpha = (const float*)d_in[2];
    const float* time_beta  = (const float*)d_in[3];
    const float* time_gamma = (const float*)d_in[4];
    const float* Wk = (const float*)d_in[5];
    const float* bk = (const float*)d_in[6];
    const float* Wv = (const float*)d_in[7];
    const float* bv = (const float*)d_in[8];
    const float* Wr = (const float*)d_in[9];
    const float* br = (const float*)d_in[10];
    const float* Wo = (const float*)d_in[11];
    const float* bo = (const float*)d_in[12];
    float* out = (float*)d_out;

    cudaFuncSetAttribute(gemm_tf,  cudaFuncAttributeMaxDynamicSharedMemorySize, SMEM_TOTAL);
    cudaFuncSetAttribute(gemm_mma, cudaFuncAttributeMaxDynamicSharedMemorySize, SMEM_TOTAL);

    // operand conversions
    conv_x_tf<<<4096, 256>>>(x);
    conv_w_tf<<<6144, 256>>>(Wk, Wv, Wr);
    conv_w_bf<<<512, 256>>>(Wo);

    // fused K/V/R projections (tf32)
    gemm_tf<<<dim3(24, 32), 256, SMEM_TOTAL>>>(bk, bv, br);

    // chunked linear recurrence
    pass_scan_local <<<dim3(4, NC, BB), 128>>>(time_w, time_alpha);
    pass_scan_carry <<<(BB * NA) / 256, 256>>>(time_w);
    pass_scan_final <<<dim3(4, NC, BB), 128>>>(time_w, time_alpha, time_beta);

    // output projection (bf16 3-term, gamma in epilogue)
    gemm_mma<<<dim3(8, 32), 256, SMEM_TOTAL>>>(bo, time_gamma, out);
}

// round 7
// speedup vs baseline: 2.9561x; 1.0604x over previous
#include <cuda_runtime.h>
#include <cuda_bf16.h>
#include <math.h>
#include <stdint.h>

// ---------------- problem constants ----------------
#define BB   4
#define TT   1024
#define HID  1024
#define NA   1024
#define CTX  1024
#define NC   16
#define CL   64

// ---------------- GEMM tiling ----------------
// CTA tile 256(M) x 128(N), K-chunk 64, 8 warps, warp tile 64x64.
#define ATILE_F 8192        // one 128x64 tf32 tile = 8192 floats = 32KB
#define STG     98304       // stage: 2 A tiles + 1 B tile = 96KB
#define SMEMT   (1024 + 2*STG)

// ---------------- static scratch ----------------
__device__ float g_k[BB*TT*NA];
__device__ float g_v[BB*TT*NA];
__device__ float g_r[BB*TT*NA];
__device__ float g_Send[BB*NC*NA];
__device__ float g_Ksum[BB*NC*NA];
__device__ float g_cS[BB*NC*NA];
__device__ float g_cK[BB*NC*NA];
// tf32 fragment-packed operands (A reused: xs for KVR, then rwkv for Wo)
__device__ __align__(16) float g_Atf[BB*TT*HID];   // 512 tiles of 128x64
__device__ __align__(16) float g_Wtf[4*HID*NA];    // 4 weights x 128 tiles

// ---------------- ptx helpers (baseline features only) ----------------
__device__ __forceinline__ uint32_t smem_u32(const void* p) {
    uint32_t a;
    asm("{ .reg .u64 t; cvta.to.shared.u64 t, %1; cvt.u32.u64 %0, t; }" : "=r"(a) : "l"(p));
    return a;
}
#define MBAR_INIT(a, c) \
    asm volatile("mbarrier.init.shared.b64 [%0], %1;" :: "r"(a), "r"(c) : "memory")
#define MBAR_EXPECT_TX(a, b) \
    asm volatile("mbarrier.arrive.expect_tx.shared.b64 _, [%0], %1;" :: "r"(a), "r"(b) : "memory")
#define MBAR_ARRIVE(a) \
    asm volatile("mbarrier.arrive.shared.b64 _, [%0];" :: "r"(a) : "memory")
#define MBAR_WAIT(a, ph) do { \
    asm volatile("{\n\t.reg .pred P;\n\tWL%=:\n\t" \
        "mbarrier.try_wait.parity.acquire.cta.shared::cta.b64 P, [%0], %1, 0x989680;\n\t" \
        "@P bra.uni WD%=;\n\tbra.uni WL%=;\n\tWD%=:\n\t}" \
        :: "r"(a), "r"(ph) : "memory"); } while (0)

__device__ __forceinline__ void bulk_ldg(uint32_t dst, const void* src, uint32_t bytes, uint32_t mbar) {
    asm volatile("cp.async.bulk.shared::cluster.global.mbarrier::complete_tx::bytes [%0], [%1], %2, [%3];"
        :: "r"(dst), "l"((unsigned long long)__cvta_generic_to_global(src)), "r"(bytes), "r"(mbar) : "memory");
}
__device__ __forceinline__ void mma1688tf(float* d, const uint32_t* a, const uint32_t* b) {
    asm volatile("mma.sync.aligned.m16n8k8.row.col.f32.tf32.tf32.f32 "
        "{%0,%1,%2,%3}, {%4,%5,%6,%7}, {%8,%9}, {%0,%1,%2,%3};"
        : "+f"(d[0]), "+f"(d[1]), "+f"(d[2]), "+f"(d[3])
        : "r"(a[0]), "r"(a[1]), "r"(a[2]), "r"(a[3]), "r"(b[0]), "r"(b[1]));
}
__device__ __forceinline__ uint32_t tf32r(float v) {
    uint32_t r;
    asm("cvt.rna.tf32.f32 %0, %1;" : "=r"(r) : "f"(v));
    return r;
}
// x with RWKV time shift
__device__ __forceinline__ float ldx(const float* __restrict__ x, int m, int k) {
    const int t = m & (TT - 1);
    if (k < HID / 2) return (t > 0) ? x[(size_t)(m - 1) * HID + k] : 0.f;
    return x[(size_t)m * HID + k];
}

// ---------------- conv: xs -> tf32 fragment-packed A tiles ----------------
// A frag map (mma.m16n8k8.tf32): a0=(m0,k0), a1=(m0+8,k0), a2=(m0,k0+4), a3=(m0+8,k0+4)
// tile layout: [g = s*8 + mf][l][4 slots], g<64, 16B per (g,l) cell.
__global__ __launch_bounds__(256)
void conv_x_tf(const float* __restrict__ x)
{
    const int idx = blockIdx.x * 256 + threadIdx.x;
    const int l = idx & 31;
    const int g = (idx >> 5) & 63;       // g = s*8 + mf
    const int tile = idx >> 11;          // tile = tm128*16 + tk
    const int tm = tile >> 4, tk = tile & 15;
    const int s = g >> 3, mf = g & 7;
    const int m0 = tm * 128 + mf * 16 + (l >> 2);
    const int k0 = tk * 64 + s * 8 + (l & 3);
    float4 f;
    f.x = ldx(x, m0,     k0);
    f.y = ldx(x, m0 + 8, k0);
    f.z = ldx(x, m0,     k0 + 4);
    f.w = ldx(x, m0 + 8, k0 + 4);
    uint4 q;
    q.x = tf32r(f.x); q.y = tf32r(f.y); q.z = tf32r(f.z); q.w = tf32r(f.w);
    *(uint4*)(g_Atf + (size_t)tile * ATILE_F + (size_t)(g * 32 + l) * 4) = q;
}

// ---------------- conv: Wk/Wv/Wr/Wo -> tf32 paired-fragment B tiles ----------------
// B frag map: b0=(k0, n), b1=(k0+4, n).  Pair-packed: cell (gp = s*8+fp, l) holds
// uint4 = {b0(f=2fp), b1(f=2fp), b0(f=2fp+1), b1(f=2fp+1)}  so one LDS.128 = 2 n-tiles.
__global__ __launch_bounds__(256)
void conv_w_tf(const float* __restrict__ Wk, const float* __restrict__ Wv,
               const float* __restrict__ Wr, const float* __restrict__ Wo)
{
    const int idx = blockIdx.x * 256 + threadIdx.x;   // 512 tiles * 64 gp * 32 l
    const int l = idx & 31;
    const int gp = (idx >> 5) & 63;      // gp = s*8 + fp
    const int tile = idx >> 11;          // tile = widx*128 + tn*16 + tk
    const int widx = tile >> 7;
    const int rem = tile & 127;
    const int tn = rem >> 4, tk = rem & 15;
    const int s = gp >> 3, fp = gp & 7;
    const int k0 = tk * 64 + s * 8 + (l & 3);
    const int ne = tn * 128 + fp * 16 + (l >> 2);     // f=2fp -> n = f*8 + (l>>2)
    const float* W = (widx == 0) ? Wk : (widx == 1) ? Wv : (widx == 2) ? Wr : Wo;
    uint4 q;
    q.x = tf32r(W[(size_t)k0 * NA + ne]);
    q.y = tf32r(W[(size_t)(k0 + 4) * NA + ne]);
    q.z = tf32r(W[(size_t)k0 * NA + ne + 8]);
    q.w = tf32r(W[(size_t)(k0 + 4) * NA + ne + 8]);
    *(uint4*)(g_Wtf + (size_t)tile * ATILE_F + (size_t)(gp * 32 + l) * 4) = q;
}

// ---------------- tf32 GEMM: C[4096, 1024-slice] = A @ W (+bias, +act) ----------------
// CTA 256x128, warp tile 64x64.  widx: 0=K(exp-clip) 1=V 2=R(sigmoid) 3=Wo(*gamma, ->obuf)
__global__ __launch_bounds__(256, 1)
void gemm_tf(int widx_fixed,
             const float* __restrict__ bk, const float* __restrict__ bv,
             const float* __restrict__ br, const float* __restrict__ bo,
             const float* __restrict__ gamma, float* __restrict__ obuf)
{
    extern __shared__ char smem_raw[];
    char* smem_al = (char*)(((uintptr_t)smem_raw + 1023) & ~(uintptr_t)1023);
    const uint32_t sb = smem_u32(smem_al);
    const int tid = threadIdx.x, l = tid & 31, w = tid >> 5;
    const int wm = w & 3, wn = w >> 2;        // 4 M-warps x 2 N-warps
    int widx, tn;
    if (widx_fixed >= 0) { widx = widx_fixed; tn = blockIdx.x; }
    else                 { widx = blockIdx.x >> 3; tn = blockIdx.x & 7; }
    const int tm = blockIdx.y;                // 16 tiles of 256 rows

    if (tid == 0) {
        MBAR_INIT(sb + 0, 1);
        MBAR_INIT(sb + 8, 1);
        MBAR_INIT(sb + 64, 256);
        MBAR_INIT(sb + 72, 256);
    }
    __syncthreads();

    const float* A0 = g_Atf + ((size_t)(tm * 2)     * 16) * ATILE_F;
    const float* A1 = g_Atf + ((size_t)(tm * 2 + 1) * 16) * ATILE_F;
    const float* Bw = g_Wtf + ((size_t)(widx * 8 + tn) * 16) * ATILE_F;

    if (tid == 0) {
#pragma unroll
        for (int c = 0; c < 2; c++) {
            const uint32_t st = sb + 1024 + c * STG;
            MBAR_EXPECT_TX(sb + 8 * c, STG);
            bulk_ldg(st,         A0 + (size_t)c * ATILE_F, 32768, sb + 8 * c);
            bulk_ldg(st + 32768, A1 + (size_t)c * ATILE_F, 32768, sb + 8 * c);
            bulk_ldg(st + 65536, Bw + (size_t)c * ATILE_F, 32768, sb + 8 * c);
        }
    }

    float acc[4][8][4];
#pragma unroll
    for (int i = 0; i < 4; i++)
#pragma unroll
        for (int j = 0; j < 8; j++)
#pragma unroll
            for (int q = 0; q < 4; q++) acc[i][j][q] = 0.f;

    // A: warp wm reads half-tile (wm>>1), m16-frags mf = (wm&1)*4 + mt
    // B: gp = ks*8 + wn*4 + ntp  -> n-tile pair (2*(wn*4+ntp), +1)
    const uint32_t a_wbase = (uint32_t)(wm >> 1) * 32768 + ((uint32_t)(wm & 1) * 4 * 32 + l) * 16;
    const uint32_t b_wbase = 65536u + ((uint32_t)wn * 4 * 32 + l) * 16;

    for (int c = 0; c < 16; c++) {
        const int s = c & 1;
        const uint32_t par = (uint32_t)((c >> 1) & 1);
        MBAR_WAIT(sb + 8 * s, par);
        const char* stp = smem_al + 1024 + s * STG;
        const char* ap = stp + a_wbase;
        const char* bp = stp + b_wbase;
#pragma unroll 2
        for (int ks = 0; ks < 8; ks++) {
            uint4 Aq[4], Bq[4];
#pragma unroll
            for (int mt = 0; mt < 4; mt++)
                Aq[mt] = *(const uint4*)(ap + (uint32_t)(ks * 8 + mt) * 512);
#pragma unroll
            for (int ntp = 0; ntp < 4; ntp++)
                Bq[ntp] = *(const uint4*)(bp + (uint32_t)(ks * 8 + ntp) * 512);
#pragma unroll
            for (int mt = 0; mt < 4; mt++) {
                const uint32_t Af[4] = {Aq[mt].x, Aq[mt].y, Aq[mt].z, Aq[mt].w};
#pragma unroll
                for (int ntp = 0; ntp < 4; ntp++) {
                    const uint32_t B0[2] = {Bq[ntp].x, Bq[ntp].y};
                    const uint32_t B1[2] = {Bq[ntp].z, Bq[ntp].w};
                    mma1688tf(acc[mt][2 * ntp],     Af, B0);
                    mma1688tf(acc[mt][2 * ntp + 1], Af, B1);
                }
            }
        }
        MBAR_ARRIVE(sb + 64 + 8 * s);
        if (tid == 0 && c + 2 < 16) {
            MBAR_WAIT(sb + 64 + 8 * s, par);
            const int cc = c + 2;
            const uint32_t st = sb + 1024 + s * STG;
            MBAR_EXPECT_TX(sb + 8 * s, STG);
            bulk_ldg(st,         A0 + (size_t)cc * ATILE_F, 32768, sb + 8 * s);
            bulk_ldg(st + 32768, A1 + (size_t)cc * ATILE_F, 32768, sb + 8 * s);
            bulk_ldg(st + 65536, Bw + (size_t)cc * ATILE_F, 32768, sb + 8 * s);
        }
    }

    // ---- epilogue ----
    const float* bias = (widx == 0) ? bk : (widx == 1) ? bv : (widx == 2) ? br : bo;
    float* out = (widx == 0) ? g_k : (widx == 1) ? g_v : (widx == 2) ? g_r : obuf;
    const int mrow_base = tm * 256 + wm * 64;
    const int col_base  = tn * 128 + wn * 64;
#pragma unroll
    for (int mt = 0; mt < 4; mt++) {
#pragma unroll
        for (int nt = 0; nt < 8; nt++) {
            const int r0 = mrow_base + mt * 16 + (l >> 2);
            const int cb = col_base + nt * 8 + (l & 3) * 2;
            const float b0 = bias[cb], b1 = bias[cb + 1];
#pragma unroll
            for (int half = 0; half < 2; half++) {
                const int row = r0 + half * 8;
                float v0 = acc[mt][nt][half * 2]     + b0;
                float v1 = acc[mt][nt][half * 2 + 1] + b1;
                if (widx == 0) {
                    v0 = expf(fminf(fmaxf(v0, -60.f), 30.f));
                    v1 = expf(fminf(fmaxf(v1, -60.f), 30.f));
                } else if (widx == 2) {
                    v0 = 1.f / (1.f + expf(-v0));
                    v1 = 1.f / (1.f + expf(-v1));
                } else if (widx == 3) {
                    const float gm = gamma[row & (TT - 1)];
                    v0 *= gm; v1 *= gm;
                }
                *(float2*)(out + (size_t)row * NA + cb) = make_float2(v0, v1);
            }
        }
    }
}

// ---------------- chunked linear scan (float2 per thread) ----------------
__global__ void pass_scan_local(const float* __restrict__ time_w,
                                const float* __restrict__ time_alpha)
{
    const int p = blockIdx.x * 128 + threadIdx.x;
    const int n = p * 2;
    const int j = blockIdx.y;
    const int b = blockIdx.z;
    const int h = n >> 4;
    const float wlast = time_w[h * CTX + CTX - 1];
    const float ratio = time_w[h * CTX + CTX - 2] / wlast;
    float S0 = 0.f, S1 = 0.f, k0 = 0.f, k1 = 0.f;
    const size_t base = ((size_t)(b * TT + j * CL)) * NA + n;
    const float* al = time_alpha + h * CTX + j * CL;
#pragma unroll 4
    for (int u = 0; u < CL; u++) {
        const float2 kk = *(const float2*)(g_k + base + (size_t)u * NA);
        const float2 vv = *(const float2*)(g_v + base + (size_t)u * NA);
        const float wa = wlast * al[u];
        S0 = fmaf(S0, ratio, wa * kk.x * vv.x);
        S1 = fmaf(S1, ratio, wa * kk.y * vv.y);
        k0 += kk.x; k1 += kk.y;
    }
    const int o = (b * NC + j) * NA + n;
    *(float2*)(g_Send + o) = make_float2(S0, S1);
    *(float2*)(g_Ksum + o) = make_float2(k0, k1);
}

__global__ void pass_scan_carry(const float* __restrict__ time_w)
{
    const int idx = blockIdx.x * 256 + threadIdx.x;
    const int n = idx & (NA - 1);
    const int b = idx >> 10;
    const int h = n >> 4;
    const float ratio = time_w[h * CTX + CTX - 2] / time_w[h * CTX + CTX - 1];
    float rL = ratio;
#pragma unroll
    for (int i = 0; i < 6; i++) rL *= rL;   // ratio^64
    float cS = 0.f, cK = 0.f;
    for (int j = 0; j < NC; j++) {
        const int o = (b * NC + j) * NA + n;
        g_cS[o] = cS;
        g_cK[o] = cK;
        cS = cS * rL + g_Send[o];
        cK += g_Ksum[o];
    }
}

// final: rwkv = sigmoid(r)*beta*S/ks, written as tf32 fragment-packed A tiles (into g_Atf)
__global__ void pass_scan_final(const float* __restrict__ time_w,
                                const float* __restrict__ time_alpha,
                                const float* __restrict__ time_beta)
{
    const int p = blockIdx.x * 128 + threadIdx.x;
    const int n = p * 2;
    const int j = blockIdx.y;
    const int b = blockIdx.z;
    const int h = n >> 4;
    const float wlast = time_w[h * CTX + CTX - 1];
    const float ratio = time_w[h * CTX + CTX - 2] / wlast;
    const int o = (b * NC + j) * NA + n;
    float2 S  = *(float2*)(g_cS + o);
    float2 ks = *(float2*)(g_cK + o);
    const size_t base = ((size_t)(b * TT + j * CL)) * NA + n;
    const float* al = time_alpha + h * CTX + j * CL;
    const float* be = time_beta  + h * CTX + j * CL;
    // channel-derived invariants of the fragment address
    const int s_n   = (n & 63) >> 3;
    const int n3    = n & 3;
    const int slotn = ((n & 7) >= 4) ? 2 : 0;
    const int tkcol = n >> 6;
#pragma unroll 4
    for (int u = 0; u < CL; u++) {
        const size_t off = base + (size_t)u * NA;
        const float2 kk = *(const float2*)(g_k + off);
        const float2 vv = *(const float2*)(g_v + off);
        const float2 sr = *(const float2*)(g_r + off);
        const float wa = wlast * al[u];
        S.x = fmaf(S.x, ratio, wa * kk.x * vv.x);
        S.y = fmaf(S.y, ratio, wa * kk.y * vv.y);
        ks.x += kk.x; ks.y += kk.y;
        const float v0 = sr.x * be[u] * S.x / ks.x;
        const float v1 = sr.y * be[u] * S.y / ks.y;
        const int tg    = j * CL + u;                       // time index
        const int tile  = (b * 8 + (tg >> 7)) * 16 + tkcol;
        const int mf    = (tg & 127) >> 4;
        const int rowin = tg & 15;
        const int slot  = (rowin >> 3) + slotn;
        const int lfrag = (rowin & 7) * 4 + n3;
        const int g     = s_n * 8 + mf;
        float* dst = g_Atf + (size_t)tile * ATILE_F + (size_t)(g * 32 + lfrag) * 4 + slot;
        dst[0] = __uint_as_float(tf32r(v0));
        dst[4] = __uint_as_float(tf32r(v1));   // lfrag+1 -> +4 floats, same slot
    }
}

// ---------------- launch ----------------
extern "C" void kernel_launch(void* const* d_in, const int* in_sizes, int n_in,
                              void* d_out, int out_size)
{
    const float* x          = (const float*)d_in[0];
    const float* time_w     = (const float*)d_in[1];
    const float* time_alpha = (const float*)d_in[2];
    const float* time_beta  = (const float*)d_in[3];
    const float* time_gamma = (const float*)d_in[4];
    const float* Wk = (const float*)d_in[5];
    const float* bk = (const float*)d_in[6];
    const float* Wv = (const float*)d_in[7];
    const float* bv = (const float*)d_in[8];
    const float* Wr = (const float*)d_in[9];
    const float* br = (const float*)d_in[10];
    const float* Wo = (const float*)d_in[11];
    const float* bo = (const float*)d_in[12];
    float* out = (float*)d_out;

    cudaFuncSetAttribute(gemm_tf, cudaFuncAttributeMaxDynamicSharedMemorySize, SMEMT);

    // operand conversions
    conv_x_tf<<<4096, 256>>>(x);
    conv_w_tf<<<4096, 256>>>(Wk, Wv, Wr, Wo);

    // fused K/V/R projections (tf32, CTA 256x128)
    gemm_tf<<<dim3(24, 16), 256, SMEMT>>>(-1, bk, bv, br, bo, time_gamma, out);

    // chunked linear recurrence; writes rwkv into g_Atf (tf32 fragment layout)
    pass_scan_local <<<dim3(4, NC, BB), 128>>>(time_w, time_alpha);
    pass_scan_carry <<<(BB * NA) / 256, 256>>>(time_w);
    pass_scan_final <<<dim3(4, NC, BB), 128>>>(time_w, time_alpha, time_beta);

    // output projection (tf32) with gamma epilogue
    gemm_tf<<<dim3(8, 16), 256, SMEMT>>>(3, bk, bv, br, bo, time_gamma, out);
}

// round 8
// speedup vs baseline: 3.4397x; 1.1636x over previous
#include <cuda_runtime.h>
#include <cuda_bf16.h>
#include <math.h>
#include <stdint.h>

// ---------------- problem constants ----------------
#define BB   4
#define TT   1024
#define HID  1024
#define NA   1024
#define CTX  1024
#define NC   32
#define CL   32

// ---------------- GEMM tiling ----------------
// CTA tile 256(M) x 128(N), K-chunk 64, 8 warps, warp tile 64x64.
#define ATILE_F 8192        // one 128x64 tf32 tile = 8192 floats = 32KB
#define STG     98304       // stage: 2 A tiles + 1 B tile = 96KB
#define SMEMT   (1024 + 2*STG)

// ---------------- static scratch ----------------
__device__ float g_k[BB*TT*NA];
__device__ float g_v[BB*TT*NA];
__device__ float g_r[BB*TT*NA];
__device__ float g_Send[BB*NC*NA];
__device__ float g_Ksum[BB*NC*NA];
__device__ float g_cS[BB*NC*NA];
__device__ float g_cK[BB*NC*NA];
// tf32 fragment-packed operands (A reused: xs for KVR, then rwkv for Wo)
__device__ __align__(16) float g_Atf[BB*TT*HID];   // 512 tiles of 128x64
__device__ __align__(16) float g_Wtf[4*HID*NA];    // 4 weights x 128 tiles

// ---------------- ptx helpers (baseline features only) ----------------
__device__ __forceinline__ uint32_t smem_u32(const void* p) {
    uint32_t a;
    asm("{ .reg .u64 t; cvta.to.shared.u64 t, %1; cvt.u32.u64 %0, t; }" : "=r"(a) : "l"(p));
    return a;
}
#define MBAR_INIT(a, c) \
    asm volatile("mbarrier.init.shared.b64 [%0], %1;" :: "r"(a), "r"(c) : "memory")
#define MBAR_EXPECT_TX(a, b) \
    asm volatile("mbarrier.arrive.expect_tx.shared.b64 _, [%0], %1;" :: "r"(a), "r"(b) : "memory")
#define MBAR_ARRIVE(a) \
    asm volatile("mbarrier.arrive.shared.b64 _, [%0];" :: "r"(a) : "memory")
#define MBAR_WAIT(a, ph) do { \
    asm volatile("{\n\t.reg .pred P;\n\tWL%=:\n\t" \
        "mbarrier.try_wait.parity.acquire.cta.shared::cta.b64 P, [%0], %1, 0x989680;\n\t" \
        "@P bra.uni WD%=;\n\tbra.uni WL%=;\n\tWD%=:\n\t}" \
        :: "r"(a), "r"(ph) : "memory"); } while (0)

__device__ __forceinline__ void bulk_ldg(uint32_t dst, const void* src, uint32_t bytes, uint32_t mbar) {
    asm volatile("cp.async.bulk.shared::cluster.global.mbarrier::complete_tx::bytes [%0], [%1], %2, [%3];"
        :: "r"(dst), "l"((unsigned long long)__cvta_generic_to_global(src)), "r"(bytes), "r"(mbar) : "memory");
}
__device__ __forceinline__ void mma1688tf(float* d, const uint32_t* a, const uint32_t* b) {
    asm volatile("mma.sync.aligned.m16n8k8.row.col.f32.tf32.tf32.f32 "
        "{%0,%1,%2,%3}, {%4,%5,%6,%7}, {%8,%9}, {%0,%1,%2,%3};"
        : "+f"(d[0]), "+f"(d[1]), "+f"(d[2]), "+f"(d[3])
        : "r"(a[0]), "r"(a[1]), "r"(a[2]), "r"(a[3]), "r"(b[0]), "r"(b[1]));
}
__device__ __forceinline__ uint32_t tf32r(float v) {
    uint32_t r;
    asm("cvt.rna.tf32.f32 %0, %1;" : "=r"(r) : "f"(v));
    return r;
}
// x with RWKV time shift
__device__ __forceinline__ float ldx(const float* __restrict__ x, int m, int k) {
    const int t = m & (TT - 1);
    if (k < HID / 2) return (t > 0) ? x[(size_t)(m - 1) * HID + k] : 0.f;
    return x[(size_t)m * HID + k];
}

// ---------------- merged conversion: xs -> A tiles, W* -> B tiles ----------------
// blockIdx.x < 4096: A path.  >= 4096: B path.
// A frag map (m16n8k8.tf32): a0=(m0,k0), a1=(m0+8,k0), a2=(m0,k0+4), a3=(m0+8,k0+4)
// B pair-packed: cell (gp=s*8+fp, l) = {b0(f=2fp), b1(f=2fp), b0(f=2fp+1), b1(f=2fp+1)}
__global__ __launch_bounds__(256)
void conv_all(const float* __restrict__ x,
              const float* __restrict__ Wk, const float* __restrict__ Wv,
              const float* __restrict__ Wr, const float* __restrict__ Wo)
{
    if (blockIdx.x < 4096) {
        const int idx = blockIdx.x * 256 + threadIdx.x;
        const int l = idx & 31;
        const int g = (idx >> 5) & 63;       // g = s*8 + mf
        const int tile = idx >> 11;          // tile = tm128*16 + tk
        const int tm = tile >> 4, tk = tile & 15;
        const int s = g >> 3, mf = g & 7;
        const int m0 = tm * 128 + mf * 16 + (l >> 2);
        const int k0 = tk * 64 + s * 8 + (l & 3);
        uint4 q;
        q.x = tf32r(ldx(x, m0,     k0));
        q.y = tf32r(ldx(x, m0 + 8, k0));
        q.z = tf32r(ldx(x, m0,     k0 + 4));
        q.w = tf32r(ldx(x, m0 + 8, k0 + 4));
        *(uint4*)(g_Atf + (size_t)tile * ATILE_F + (size_t)(g * 32 + l) * 4) = q;
    } else {
        const int idx = (blockIdx.x - 4096) * 256 + threadIdx.x;
        const int l = idx & 31;
        const int gp = (idx >> 5) & 63;      // gp = s*8 + fp
        const int tile = idx >> 11;          // tile = widx*128 + tn*16 + tk
        const int widx = tile >> 7;
        const int rem = tile & 127;
        const int tn = rem >> 4, tk = rem & 15;
        const int s = gp >> 3, fp = gp & 7;
        const int k0 = tk * 64 + s * 8 + (l & 3);
        const int ne = tn * 128 + fp * 16 + (l >> 2);
        const float* W = (widx == 0) ? Wk : (widx == 1) ? Wv : (widx == 2) ? Wr : Wo;
        uint4 q;
        q.x = tf32r(W[(size_t)k0 * NA + ne]);
        q.y = tf32r(W[(size_t)(k0 + 4) * NA + ne]);
        q.z = tf32r(W[(size_t)k0 * NA + ne + 8]);
        q.w = tf32r(W[(size_t)(k0 + 4) * NA + ne + 8]);
        *(uint4*)(g_Wtf + (size_t)tile * ATILE_F + (size_t)(gp * 32 + l) * 4) = q;
    }
}

// ---------------- tf32 GEMM: C[4096, 1024-slice] = A @ W (+bias, +act) ----------------
// CTA 256x128, warp tile 64x64.  widx: 0=K(exp-clip) 1=V 2=R(sigmoid) 3=Wo(*gamma, ->obuf)
__global__ __launch_bounds__(256, 1)
void gemm_tf(int widx_fixed,
             const float* __restrict__ bk, const float* __restrict__ bv,
             const float* __restrict__ br, const float* __restrict__ bo,
             const float* __restrict__ gamma, float* __restrict__ obuf)
{
    extern __shared__ char smem_raw[];
    char* smem_al = (char*)(((uintptr_t)smem_raw + 1023) & ~(uintptr_t)1023);
    const uint32_t sb = smem_u32(smem_al);
    const int tid = threadIdx.x, l = tid & 31, w = tid >> 5;
    const int wm = w & 3, wn = w >> 2;        // 4 M-warps x 2 N-warps
    int widx, tn;
    if (widx_fixed >= 0) { widx = widx_fixed; tn = blockIdx.x; }
    else                 { widx = blockIdx.x >> 3; tn = blockIdx.x & 7; }
    const int tm = blockIdx.y;                // 16 tiles of 256 rows

    if (tid == 0) {
        MBAR_INIT(sb + 0, 1);
        MBAR_INIT(sb + 8, 1);
        MBAR_INIT(sb + 64, 256);
        MBAR_INIT(sb + 72, 256);
    }
    __syncthreads();

    const float* A0 = g_Atf + ((size_t)(tm * 2)     * 16) * ATILE_F;
    const float* A1 = g_Atf + ((size_t)(tm * 2 + 1) * 16) * ATILE_F;
    const float* Bw = g_Wtf + ((size_t)(widx * 8 + tn) * 16) * ATILE_F;

    if (tid == 0) {
#pragma unroll
        for (int c = 0; c < 2; c++) {
            const uint32_t st = sb + 1024 + c * STG;
            MBAR_EXPECT_TX(sb + 8 * c, STG);
            bulk_ldg(st,         A0 + (size_t)c * ATILE_F, 32768, sb + 8 * c);
            bulk_ldg(st + 32768, A1 + (size_t)c * ATILE_F, 32768, sb + 8 * c);
            bulk_ldg(st + 65536, Bw + (size_t)c * ATILE_F, 32768, sb + 8 * c);
        }
    }

    float acc[4][8][4];
#pragma unroll
    for (int i = 0; i < 4; i++)
#pragma unroll
        for (int j = 0; j < 8; j++)
#pragma unroll
            for (int q = 0; q < 4; q++) acc[i][j][q] = 0.f;

    const uint32_t a_wbase = (uint32_t)(wm >> 1) * 32768 + ((uint32_t)(wm & 1) * 4 * 32 + l) * 16;
    const uint32_t b_wbase = 65536u + ((uint32_t)wn * 4 * 32 + l) * 16;

    for (int c = 0; c < 16; c++) {
        const int s = c & 1;
        const uint32_t par = (uint32_t)((c >> 1) & 1);
        MBAR_WAIT(sb + 8 * s, par);
        const char* stp = smem_al + 1024 + s * STG;
        const char* ap = stp + a_wbase;
        const char* bp = stp + b_wbase;
#pragma unroll 2
        for (int ks = 0; ks < 8; ks++) {
            uint4 Aq[4], Bq[4];
#pragma unroll
            for (int mt = 0; mt < 4; mt++)
                Aq[mt] = *(const uint4*)(ap + (uint32_t)(ks * 8 + mt) * 512);
#pragma unroll
            for (int ntp = 0; ntp < 4; ntp++)
                Bq[ntp] = *(const uint4*)(bp + (uint32_t)(ks * 8 + ntp) * 512);
#pragma unroll
            for (int mt = 0; mt < 4; mt++) {
                const uint32_t Af[4] = {Aq[mt].x, Aq[mt].y, Aq[mt].z, Aq[mt].w};
#pragma unroll
                for (int ntp = 0; ntp < 4; ntp++) {
                    const uint32_t B0[2] = {Bq[ntp].x, Bq[ntp].y};
                    const uint32_t B1[2] = {Bq[ntp].z, Bq[ntp].w};
                    mma1688tf(acc[mt][2 * ntp],     Af, B0);
                    mma1688tf(acc[mt][2 * ntp + 1], Af, B1);
                }
            }
        }
        MBAR_ARRIVE(sb + 64 + 8 * s);
        if (tid == 0 && c + 2 < 16) {
            MBAR_WAIT(sb + 64 + 8 * s, par);
            const int cc = c + 2;
            const uint32_t st = sb + 1024 + s * STG;
            MBAR_EXPECT_TX(sb + 8 * s, STG);
            bulk_ldg(st,         A0 + (size_t)cc * ATILE_F, 32768, sb + 8 * s);
            bulk_ldg(st + 32768, A1 + (size_t)cc * ATILE_F, 32768, sb + 8 * s);
            bulk_ldg(st + 65536, Bw + (size_t)cc * ATILE_F, 32768, sb + 8 * s);
        }
    }

    // ---- epilogue ----
    const float* bias = (widx == 0) ? bk : (widx == 1) ? bv : (widx == 2) ? br : bo;
    float* out = (widx == 0) ? g_k : (widx == 1) ? g_v : (widx == 2) ? g_r : obuf;
    const int mrow_base = tm * 256 + wm * 64;
    const int col_base  = tn * 128 + wn * 64;
#pragma unroll
    for (int mt = 0; mt < 4; mt++) {
#pragma unroll
        for (int nt = 0; nt < 8; nt++) {
            const int r0 = mrow_base + mt * 16 + (l >> 2);
            const int cb = col_base + nt * 8 + (l & 3) * 2;
            const float b0 = bias[cb], b1 = bias[cb + 1];
#pragma unroll
            for (int half = 0; half < 2; half++) {
                const int row = r0 + half * 8;
                float v0 = acc[mt][nt][half * 2]     + b0;
                float v1 = acc[mt][nt][half * 2 + 1] + b1;
                if (widx == 0) {
                    v0 = __expf(fminf(fmaxf(v0, -60.f), 30.f));
                    v1 = __expf(fminf(fmaxf(v1, -60.f), 30.f));
                } else if (widx == 2) {
                    v0 = __fdividef(1.f, 1.f + __expf(-v0));
                    v1 = __fdividef(1.f, 1.f + __expf(-v1));
                } else if (widx == 3) {
                    const float gm = gamma[row & (TT - 1)];
                    v0 *= gm; v1 *= gm;
                }
                *(float2*)(out + (size_t)row * NA + cb) = make_float2(v0, v1);
            }
        }
    }
}

// ---------------- chunked linear scan (1 channel/thread, 256-thread blocks) ----------------
__global__ __launch_bounds__(256)
void pass_scan_local(const float* __restrict__ time_w,
                     const float* __restrict__ time_alpha)
{
    const int n = blockIdx.x * 256 + threadIdx.x;
    const int j = blockIdx.y;
    const int b = blockIdx.z;
    const int h = n >> 4;
    const float wlast = time_w[h * CTX + CTX - 1];
    const float ratio = time_w[h * CTX + CTX - 2] / wlast;
    float S = 0.f, ks = 0.f;
    const size_t base = ((size_t)(b * TT + j * CL)) * NA + n;
    const float* al = time_alpha + h * CTX + j * CL;
#pragma unroll 8
    for (int u = 0; u < CL; u++) {
        const float kk = g_k[base + (size_t)u * NA];
        const float vv = g_v[base + (size_t)u * NA];
        S  = fmaf(S, ratio, wlast * al[u] * kk * vv);
        ks += kk;
    }
    const int o = (b * NC + j) * NA + n;
    g_Send[o] = S;
    g_Ksum[o] = ks;
}

__global__ __launch_bounds__(256)
void pass_scan_carry(const float* __restrict__ time_w)
{
    const int idx = blockIdx.x * 256 + threadIdx.x;
    const int n = idx & (NA - 1);
    const int b = idx >> 10;
    const int h = n >> 4;
    const float ratio = time_w[h * CTX + CTX - 2] / time_w[h * CTX + CTX - 1];
    float rL = ratio;
#pragma unroll
    for (int i = 0; i < 5; i++) rL *= rL;   // ratio^32 (CL=32)
    float cS = 0.f, cK = 0.f;
    for (int j = 0; j < NC; j++) {
        const int o = (b * NC + j) * NA + n;
        g_cS[o] = cS;
        g_cK[o] = cK;
        cS = cS * rL + g_Send[o];
        cK += g_Ksum[o];
    }
}

// final: rwkv = sigmoid(r)*beta*S/ks, written as tf32 fragment-packed A tiles (into g_Atf)
__global__ __launch_bounds__(256)
void pass_scan_final(const float* __restrict__ time_w,
                     const float* __restrict__ time_alpha,
                     const float* __restrict__ time_beta)
{
    const int n = blockIdx.x * 256 + threadIdx.x;
    const int j = blockIdx.y;
    const int b = blockIdx.z;
    const int h = n >> 4;
    const float wlast = time_w[h * CTX + CTX - 1];
    const float ratio = time_w[h * CTX + CTX - 2] / wlast;
    const int o = (b * NC + j) * NA + n;
    float S  = g_cS[o];
    float ks = g_cK[o];
    const size_t base = ((size_t)(b * TT + j * CL)) * NA + n;
    const float* al = time_alpha + h * CTX + j * CL;
    const float* be = time_beta  + h * CTX + j * CL;
    // channel-derived invariants of the fragment address
    const int s_n   = (n & 63) >> 3;
    const int n3    = n & 3;
    const int slotn = ((n & 7) >= 4) ? 2 : 0;
    const int tkcol = n >> 6;
    const int lbase = n3;                    // lfrag = (rowin&7)*4 + n3
#pragma unroll 8
    for (int u = 0; u < CL; u++) {
        const size_t off = base + (size_t)u * NA;
        const float kk = g_k[off];
        const float vv = g_v[off];
        const float sr = g_r[off];
        S  = fmaf(S, ratio, wlast * al[u] * kk * vv);
        ks += kk;
        const float val = sr * be[u] * __fdividef(S, ks);
        const int tg    = j * CL + u;
        const int tile  = (b * 8 + (tg >> 7)) * 16 + tkcol;
        const int mf    = (tg & 127) >> 4;
        const int rowin = tg & 15;
        const int slot  = (rowin >> 3) + slotn;
        const int lfrag = (rowin & 7) * 4 + lbase;
        const int g     = s_n * 8 + mf;
        g_Atf[(size_t)tile * ATILE_F + (size_t)(g * 32 + lfrag) * 4 + slot]
            = __uint_as_float(tf32r(val));
    }
}

// ---------------- launch ----------------
extern "C" void kernel_launch(void* const* d_in, const int* in_sizes, int n_in,
                              void* d_out, int out_size)
{
    const float* x          = (const float*)d_in[0];
    const float* time_w     = (const float*)d_in[1];
    const float* time_alpha = (const float*)d_in[2];
    const float* time_beta  = (const float*)d_in[3];
    const float* time_gamma = (const float*)d_in[4];
    const float* Wk = (const float*)d_in[5];
    const float* bk = (const float*)d_in[6];
    const float* Wv = (const float*)d_in[7];
    const float* bv = (const float*)d_in[8];
    const float* Wr = (const float*)d_in[9];
    const float* br = (const float*)d_in[10];
    const float* Wo = (const float*)d_in[11];
    const float* bo = (const float*)d_in[12];
    float* out = (float*)d_out;

    cudaFuncSetAttribute(gemm_tf, cudaFuncAttributeMaxDynamicSharedMemorySize, SMEMT);

    // merged operand conversions (A path + B path in one launch)
    conv_all<<<8192, 256>>>(x, Wk, Wv, Wr, Wo);

    // fused K/V/R projections (tf32, CTA 256x128)
    gemm_tf<<<dim3(24, 16), 256, SMEMT>>>(-1, bk, bv, br, bo, time_gamma, out);

    // chunked linear recurrence; writes rwkv into g_Atf (tf32 fragment layout)
    pass_scan_local <<<dim3(4, NC, BB), 256>>>(time_w, time_alpha);
    pass_scan_carry <<<(BB * NA) / 256, 256>>>(time_w);
    pass_scan_final <<<dim3(4, NC, BB), 256>>>(time_w, time_alpha, time_beta);

    // output projection (tf32) with gamma epilogue
    gemm_tf<<<dim3(8, 16), 256, SMEMT>>>(3, bk, bv, br, bo, time_gamma, out);
}